// round 6
// baseline (speedup 1.0000x reference)
#include <cuda_runtime.h>

#define IMG_H 2048
#define IMG_W 2048

constexpr int TW = 128;  // tile width  (32 threads x 4 cols)
constexpr int TH = 16;   // tile height (8 thread-rows x 2 rows)

__global__ __launch_bounds__(256, 5)
void plane_fit_kernel(const float* __restrict__ x, float* __restrict__ out) {
    __shared__ __align__(16) float Ssh[TH + 6][132];  // horizontal box sums
    __shared__ __align__(16) float Dsh[TH + 6][132];  // horizontal gradient sums

    const int cx  = threadIdx.x;          // 0..31 -> 4-column group
    const int ty  = threadIdx.y;          // 0..7
    const int bx0 = blockIdx.x * TW;
    const int by0 = blockIdx.y * TH;
    const int gx0 = bx0 + 4 * cx;         // first of this thread's 4 output columns

    // ================= Phase 1: horizontal pass, rows 0..TH+5 =================
    const bool interior = (gx0 - 4 >= 0) && (gx0 + 7 <= IMG_W - 1);

    #pragma unroll
    for (int j = ty; j < TH + 6; j += 8) {
        const int gy = min(max(by0 + j - 3, 0), IMG_H - 1);
        const float* __restrict__ row = x + (size_t)gy * IMG_W;

        float f[12];  // input cols gx0-4 .. gx0+7
        if (interior) {
            float4 a = *reinterpret_cast<const float4*>(row + gx0 - 4);
            float4 b = *reinterpret_cast<const float4*>(row + gx0);
            float4 c = *reinterpret_cast<const float4*>(row + gx0 + 4);
            f[0]=a.x; f[1]=a.y; f[2]=a.z;  f[3]=a.w;
            f[4]=b.x; f[5]=b.y; f[6]=b.z;  f[7]=b.w;
            f[8]=c.x; f[9]=c.y; f[10]=c.z; f[11]=c.w;
        } else {
            #pragma unroll
            for (int m = 0; m < 12; m++) {
                int gc = min(max(gx0 - 4 + m, 0), IMG_W - 1);
                f[m] = row[gc];
            }
        }

        float S0 = f[1]+f[2]+f[3]+f[4]+f[5]+f[6]+f[7];
        float S1 = S0 - f[1] + f[8];
        float S2 = S1 - f[2] + f[9];
        float S3 = S2 - f[3] + f[10];
        float D0 = -3.0f*f[1] - 2.0f*f[2] - f[3] + f[5] + 2.0f*f[6] + 3.0f*f[7];
        float D1 = D0 + 3.0f*f[1] + 4.0f*f[8]  - S1;
        float D2 = D1 + 3.0f*f[2] + 4.0f*f[9]  - S2;
        float D3 = D2 + 3.0f*f[3] + 4.0f*f[10] - S3;

        *reinterpret_cast<float4*>(&Ssh[j][4*cx]) = make_float4(S0, S1, S2, S3);
        *reinterpret_cast<float4*>(&Dsh[j][4*cx]) = make_float4(D0, D1, D2, D3);
    }
    __syncthreads();

    // ================= Phase 2: vertical pass, 2 rows x 4 cols per thread =====
    const int r0 = ty * 2;
    float4 sS[2], sY[2], sD[2];
    #pragma unroll
    for (int ri = 0; ri < 2; ri++) {
        sS[ri] = make_float4(0.f,0.f,0.f,0.f);
        sY[ri] = make_float4(0.f,0.f,0.f,0.f);
        sD[ri] = make_float4(0.f,0.f,0.f,0.f);
    }

    #pragma unroll
    for (int j = 0; j < 8; j++) {
        float4 Sj = *reinterpret_cast<const float4*>(&Ssh[r0 + j][4*cx]);
        float4 Dj = *reinterpret_cast<const float4*>(&Dsh[r0 + j][4*cx]);
        #pragma unroll
        for (int ri = 0; ri < 2; ri++) {
            const int k = j - ri;          // kernel row 0..6
            if (k >= 0 && k < 7) {
                const float w = (float)(k - 3);
                sS[ri].x += Sj.x;   sS[ri].y += Sj.y;   sS[ri].z += Sj.z;   sS[ri].w += Sj.w;
                sY[ri].x += w*Sj.x; sY[ri].y += w*Sj.y; sY[ri].z += w*Sj.z; sY[ri].w += w*Sj.w;
                sD[ri].x += Dj.x;   sD[ri].y += Dj.y;   sD[ri].z += Dj.z;   sD[ri].w += Dj.w;
            }
        }
    }

    // ================= Stores: 3 coalesced float4 per output row =================
    const float inv196 = 1.0f / 196.0f;
    const float inv49  = 1.0f / 49.0f;
    #pragma unroll
    for (int ri = 0; ri < 2; ri++) {
        const int gy = by0 + r0 + ri;
        float* __restrict__ o = out + ((size_t)gy * IMG_W + gx0) * 3;
        float4 p0 = make_float4(sD[ri].x*inv196, sY[ri].x*inv196, sS[ri].x*inv49,
                                sD[ri].y*inv196);
        float4 p1 = make_float4(sY[ri].y*inv196, sS[ri].y*inv49,
                                sD[ri].z*inv196, sY[ri].z*inv196);
        float4 p2 = make_float4(sS[ri].z*inv49,
                                sD[ri].w*inv196, sY[ri].w*inv196, sS[ri].w*inv49);
        reinterpret_cast<float4*>(o)[0] = p0;
        reinterpret_cast<float4*>(o)[1] = p1;
        reinterpret_cast<float4*>(o)[2] = p2;
    }
}

extern "C" void kernel_launch(void* const* d_in, const int* in_sizes, int n_in,
                              void* d_out, int out_size) {
    const float* x = (const float*)d_in[0];
    float* out = (float*)d_out;
    dim3 block(32, 8);
    dim3 grid(IMG_W / TW, IMG_H / TH);
    plane_fit_kernel<<<grid, block>>>(x, out);
}

// round 7
// speedup vs baseline: 1.0125x; 1.0125x over previous
#include <cuda_runtime.h>

#define IMG_H 2048
#define IMG_W 2048

constexpr int TW = 128;  // tile width  (32 threads x 4 cols)
constexpr int TH = 16;   // tile height (8 thread-rows x 2 rows)

__device__ __forceinline__ float4 f4add(float4 a, float4 b) {
    return make_float4(a.x+b.x, a.y+b.y, a.z+b.z, a.w+b.w);
}
__device__ __forceinline__ float4 f4sub(float4 a, float4 b) {
    return make_float4(a.x-b.x, a.y-b.y, a.z-b.z, a.w-b.w);
}
__device__ __forceinline__ float4 f4fma(float w, float4 a, float4 acc) {
    return make_float4(fmaf(w,a.x,acc.x), fmaf(w,a.y,acc.y),
                       fmaf(w,a.z,acc.z), fmaf(w,a.w,acc.w));
}

__global__ __launch_bounds__(256, 6)
void plane_fit_kernel(const float* __restrict__ x, float* __restrict__ out) {
    __shared__ __align__(16) float Ssh[TH + 6][132];  // horizontal box sums
    __shared__ __align__(16) float Dsh[TH + 6][132];  // horizontal gradient sums

    const int cx  = threadIdx.x;          // 0..31 -> 4-column group
    const int ty  = threadIdx.y;          // 0..7
    const int bx0 = blockIdx.x * TW;
    const int by0 = blockIdx.y * TH;
    const int gx0 = bx0 + 4 * cx;

    // ================= Phase 1: horizontal pass, rows 0..TH+5 =================
    const bool interior = (gx0 - 4 >= 0) && (gx0 + 7 <= IMG_W - 1);

    #pragma unroll
    for (int j = ty; j < TH + 6; j += 8) {
        const int gy = min(max(by0 + j - 3, 0), IMG_H - 1);
        const float* __restrict__ row = x + (size_t)gy * IMG_W;

        float f[12];  // input cols gx0-4 .. gx0+7
        if (interior) {
            float4 a = *reinterpret_cast<const float4*>(row + gx0 - 4);
            float4 b = *reinterpret_cast<const float4*>(row + gx0);
            float4 c = *reinterpret_cast<const float4*>(row + gx0 + 4);
            f[0]=a.x; f[1]=a.y; f[2]=a.z;  f[3]=a.w;
            f[4]=b.x; f[5]=b.y; f[6]=b.z;  f[7]=b.w;
            f[8]=c.x; f[9]=c.y; f[10]=c.z; f[11]=c.w;
        } else {
            #pragma unroll
            for (int m = 0; m < 12; m++) {
                int gc = min(max(gx0 - 4 + m, 0), IMG_W - 1);
                f[m] = row[gc];
            }
        }

        float S0 = f[1]+f[2]+f[3]+f[4]+f[5]+f[6]+f[7];
        float S1 = S0 - f[1] + f[8];
        float S2 = S1 - f[2] + f[9];
        float S3 = S2 - f[3] + f[10];
        float D0 = -3.0f*f[1] - 2.0f*f[2] - f[3] + f[5] + 2.0f*f[6] + 3.0f*f[7];
        float D1 = D0 + 3.0f*f[1] + 4.0f*f[8]  - S1;
        float D2 = D1 + 3.0f*f[2] + 4.0f*f[9]  - S2;
        float D3 = D2 + 3.0f*f[3] + 4.0f*f[10] - S3;

        *reinterpret_cast<float4*>(&Ssh[j][4*cx]) = make_float4(S0, S1, S2, S3);
        *reinterpret_cast<float4*>(&Dsh[j][4*cx]) = make_float4(D0, D1, D2, D3);
    }
    __syncthreads();

    // ================= Phase 2: vertical 7-tap for row r0, rolled for r0+1 ====
    const int r0 = ty * 2;
    const float inv196 = 1.0f / 196.0f;
    const float inv49  = 1.0f / 49.0f;

    // keep row j=0 for the rolling update
    float4 S0 = *reinterpret_cast<const float4*>(&Ssh[r0][4*cx]);
    float4 D0 = *reinterpret_cast<const float4*>(&Dsh[r0][4*cx]);

    float4 sS = S0;
    float4 sD = D0;
    float4 sY = make_float4(-3.f*S0.x, -3.f*S0.y, -3.f*S0.z, -3.f*S0.w);

    #pragma unroll
    for (int j = 1; j < 7; j++) {
        float4 Sj = *reinterpret_cast<const float4*>(&Ssh[r0 + j][4*cx]);
        float4 Dj = *reinterpret_cast<const float4*>(&Dsh[r0 + j][4*cx]);
        const float w = (float)(j - 3);
        sS = f4add(sS, Sj);
        sY = f4fma(w, Sj, sY);
        sD = f4add(sD, Dj);
    }

    // ---- store row r0 ----
    {
        float* __restrict__ o = out + ((size_t)(by0 + r0) * IMG_W + gx0) * 3;
        float4 p0 = make_float4(sD.x*inv196, sY.x*inv196, sS.x*inv49, sD.y*inv196);
        float4 p1 = make_float4(sY.y*inv196, sS.y*inv49,  sD.z*inv196, sY.z*inv196);
        float4 p2 = make_float4(sS.z*inv49,  sD.w*inv196, sY.w*inv196, sS.w*inv49);
        __stcs(reinterpret_cast<float4*>(o) + 0, p0);
        __stcs(reinterpret_cast<float4*>(o) + 1, p1);
        __stcs(reinterpret_cast<float4*>(o) + 2, p2);
    }

    // ---- roll to row r0+1 ----
    {
        float4 S7 = *reinterpret_cast<const float4*>(&Ssh[r0 + 7][4*cx]);
        float4 D7 = *reinterpret_cast<const float4*>(&Dsh[r0 + 7][4*cx]);
        // sY' = sY - sS + 4*S0 + 3*S7   (uses OLD sS)
        float4 sY1 = f4fma(4.f, S0, f4fma(3.f, S7, f4sub(sY, sS)));
        float4 sS1 = f4add(f4sub(sS, S0), S7);
        float4 sD1 = f4add(f4sub(sD, D0), D7);

        float* __restrict__ o = out + ((size_t)(by0 + r0 + 1) * IMG_W + gx0) * 3;
        float4 p0 = make_float4(sD1.x*inv196, sY1.x*inv196, sS1.x*inv49, sD1.y*inv196);
        float4 p1 = make_float4(sY1.y*inv196, sS1.y*inv49,  sD1.z*inv196, sY1.z*inv196);
        float4 p2 = make_float4(sS1.z*inv49,  sD1.w*inv196, sY1.w*inv196, sS1.w*inv49);
        __stcs(reinterpret_cast<float4*>(o) + 0, p0);
        __stcs(reinterpret_cast<float4*>(o) + 1, p1);
        __stcs(reinterpret_cast<float4*>(o) + 2, p2);
    }
}

extern "C" void kernel_launch(void* const* d_in, const int* in_sizes, int n_in,
                              void* d_out, int out_size) {
    const float* x = (const float*)d_in[0];
    float* out = (float*)d_out;
    dim3 block(32, 8);
    dim3 grid(IMG_W / TW, IMG_H / TH);
    plane_fit_kernel<<<grid, block>>>(x, out);
}